// round 4
// baseline (speedup 1.0000x reference)
#include <cuda_runtime.h>
#include <cstdint>

#define BB 2
#define QQ 100
#define GG 10
#define TT 5
#define HH 128
#define WW 128
#define NC 41
#define NBGT (BB * GG * TT)      // 100
#define NCHUNK 4                 // row-chunks per box tile

// Scratch (no cudaMalloc allowed)
__device__ int4   d_boxpart[NBGT * NCHUNK];   // raw (ymin,ymax,xmin,xmax) per chunk
__device__ float4 d_part[BB * QQ * TT * GG];  // Ny, Sy, Nx, Sx per (b,q,t,g)

__device__ __forceinline__ float sigmoidf_fast(float x) {
    return 1.0f / (1.0f + __expf(-x));
}

// XOR-swizzled tile addressing: float4 index for (row h, float4-col w4).
__device__ __forceinline__ int sw4(int h, int w4) { return (h << 5) + (w4 ^ (h & 31)); }
__device__ __forceinline__ float tile_ld(const float* t, int h, int w) {
    return t[(sw4(h, w >> 2) << 2) + (w & 3)];
}

// Combine 4 chunk partials -> final (y0,y1,x0,x1) box (0,0,0,0 if empty).
__device__ __forceinline__ int4 combine_box(int base) {
    int4 r = d_boxpart[base];
    #pragma unroll
    for (int c = 1; c < NCHUNK; ++c) {
        int4 p = d_boxpart[base + c];
        r.x = min(r.x, p.x); r.y = max(r.y, p.y);
        r.z = min(r.z, p.z); r.w = max(r.w, p.w);
    }
    return (r.y < 0) ? make_int4(0, 0, 0, 0) : make_int4(r.x, r.y + 1, r.z, r.w + 1);
}

// ---------------------------------------------------------------------------
// Kernel 1: box partials. grid = B*G*T*4 CTAs, 256 threads, 32 rows each.
// 4 front-batched float4 loads per thread -> DRAM-saturating parallelism.
// ---------------------------------------------------------------------------
__global__ __launch_bounds__(256) void box_chunk_kernel(const float* __restrict__ bm) {
    __shared__ int4 wred[8];
    const int tid   = threadIdx.x;
    const int lane  = tid & 31;
    const int wid   = tid >> 5;
    const int bgt   = blockIdx.x >> 2;
    const int chunk = blockIdx.x & 3;
    const int row0  = chunk * 32;

    const float4* src = reinterpret_cast<const float4*>(
        bm + (size_t)bgt * (HH * WW) + (size_t)row0 * WW);

    float4 vv[4];
    #pragma unroll
    for (int k = 0; k < 4; ++k) vv[k] = src[k * 256 + tid];

    const int c0 = lane * 4;
    int ymin = HH, ymax = -1, xmin = WW, xmax = -1;
    #pragma unroll
    for (int k = 0; k < 4; ++k) {
        const int row = row0 + k * 8 + wid;
        float4 d = vv[k];
        const bool f0 = d.x > 0.5f, f1 = d.y > 0.5f, f2 = d.z > 0.5f, f3 = d.w > 0.5f;
        xmin = min(xmin, f0 ? c0     : WW);
        xmin = min(xmin, f1 ? c0 + 1 : WW);
        xmin = min(xmin, f2 ? c0 + 2 : WW);
        xmin = min(xmin, f3 ? c0 + 3 : WW);
        xmax = max(xmax, f0 ? c0     : -1);
        xmax = max(xmax, f1 ? c0 + 1 : -1);
        xmax = max(xmax, f2 ? c0 + 2 : -1);
        xmax = max(xmax, f3 ? c0 + 3 : -1);
        const bool any = f0 | f1 | f2 | f3;
        ymin = min(ymin, any ? row : HH);
        ymax = max(ymax, any ? row : -1);
    }
    #pragma unroll
    for (int o = 16; o >= 1; o >>= 1) {
        ymin = min(ymin, __shfl_xor_sync(0xffffffffu, ymin, o));
        ymax = max(ymax, __shfl_xor_sync(0xffffffffu, ymax, o));
        xmin = min(xmin, __shfl_xor_sync(0xffffffffu, xmin, o));
        xmax = max(xmax, __shfl_xor_sync(0xffffffffu, xmax, o));
    }
    if (lane == 0) wred[wid] = make_int4(ymin, ymax, xmin, xmax);
    __syncthreads();
    if (wid == 0) {
        int4 r = wred[lane & 7];
        #pragma unroll
        for (int o = 4; o >= 1; o >>= 1) {
            r.x = min(r.x, __shfl_xor_sync(0xffffffffu, r.x, o));
            r.y = max(r.y, __shfl_xor_sync(0xffffffffu, r.y, o));
            r.z = min(r.z, __shfl_xor_sync(0xffffffffu, r.z, o));
            r.w = max(r.w, __shfl_xor_sync(0xffffffffu, r.w, o));
        }
        if (lane == 0) d_boxpart[blockIdx.x] = r;   // raw partial
    }
}

// ---------------------------------------------------------------------------
// Kernel 2: main reduction. grid = B*Q*T, 256 threads, 3 CTAs/SM.
// ---------------------------------------------------------------------------
__global__ __launch_bounds__(256, 3) void main_kernel(const float* __restrict__ pm) {
    __shared__ float4 tile4[HH * 32];      // 64 KB, XOR-swizzled
    __shared__ float4 colpart4[8 * 32];
    __shared__ float  rowm[HH];
    __shared__ float  colm[WW];
    __shared__ float  sums[2];
    __shared__ int4   sbox[GG * TT];       // combined boxes for this b
    const float* tile = reinterpret_cast<const float*>(tile4);
    float* colpart = reinterpret_cast<float*>(colpart4);

    const int blk  = blockIdx.x;           // (b*Q + q)*T + t
    const int t    = blk % TT;
    const int bq   = blk / TT;
    const int b    = bq / QQ;
    const int tid  = threadIdx.x;
    const int lane = tid & 31;
    const int wid  = tid >> 5;

    // ---- combine box partials for this batch (overlaps with loads below) ----
    if (tid < GG * TT) {
        sbox[tid] = combine_box((b * GG * TT + tid) * NCHUNK);
    }

    // ---- phase 1: stream tile; fold row maxes (shfl) + col maxes (regs) ----
    const float4* src = reinterpret_cast<const float4*>(pm + (size_t)blk * (HH * WW));
    float4 cm = make_float4(-1e30f, -1e30f, -1e30f, -1e30f);
    float4 v[8];
    #pragma unroll
    for (int batch = 0; batch < 2; ++batch) {
        #pragma unroll
        for (int j2 = 0; j2 < 8; ++j2) v[j2] = src[(batch * 8 + j2) * 256 + tid];
        #pragma unroll
        for (int j2 = 0; j2 < 8; ++j2) {
            const int row = (batch * 8 + j2) * 8 + wid;
            float4 d = v[j2];
            tile4[sw4(row, lane)] = d;                          // conflict-free STS.128
            cm.x = fmaxf(cm.x, d.x); cm.y = fmaxf(cm.y, d.y);
            cm.z = fmaxf(cm.z, d.z); cm.w = fmaxf(cm.w, d.w);
            float m = fmaxf(fmaxf(d.x, d.y), fmaxf(d.z, d.w));
            #pragma unroll
            for (int o = 16; o >= 1; o >>= 1) m = fmaxf(m, __shfl_xor_sync(0xffffffffu, m, o));
            if (lane == 0) rowm[row] = m;
        }
    }
    colpart4[wid * 32 + lane] = cm;
    __syncthreads();

    // ---- combine col partials + sigmoid row/col maxes ----
    if (tid < 128) {
        float m = colpart[tid];
        #pragma unroll
        for (int w = 1; w < 8; ++w) m = fmaxf(m, colpart[w * 128 + tid]);
        colm[tid] = sigmoidf_fast(m);
    } else {
        const int r = tid - 128;
        rowm[r] = sigmoidf_fast(rowm[r]);
    }
    __syncthreads();

    // ---- full sums of sigmoided row/col maxes ----
    if (wid < 2) {
        const float* arr = (wid == 0) ? rowm : colm;
        float s = arr[lane] + arr[lane + 32] + arr[lane + 64] + arr[lane + 96];
        #pragma unroll
        for (int o = 16; o >= 1; o >>= 1) s += __shfl_xor_sync(0xffffffffu, s, o);
        if (lane == 0) sums[wid] = s;
    }
    __syncthreads();
    const float sumY = sums[0];
    const float sumX = sums[1];

    // ---- per-target box-restricted reductions (one warp per g) ----
    for (int g = wid; g < GG; g += 8) {
        const int4 bx = sbox[g * TT + t];            // y0,y1,x0,x1

        float Ny = 0.f, Ry = 0.f;
        const int w40 = bx.z >> 2;
        const int w41 = (bx.w - 1) >> 2;
        for (int h = bx.x + lane; h < bx.y; h += 32) {
            const int hs = h << 5, hx = h & 31;
            float m = -1e30f;
            for (int w4 = w40; w4 <= w41; ++w4) {
                float4 d = tile4[hs + (w4 ^ hx)];
                const int wb = w4 << 2;
                m = fmaxf(m, (wb     >= bx.z && wb     < bx.w) ? d.x : -1e30f);
                m = fmaxf(m, (wb + 1 >= bx.z && wb + 1 < bx.w) ? d.y : -1e30f);
                m = fmaxf(m, (wb + 2 >= bx.z && wb + 2 < bx.w) ? d.z : -1e30f);
                m = fmaxf(m, (wb + 3 >= bx.z && wb + 3 < bx.w) ? d.w : -1e30f);
            }
            Ny += sigmoidf_fast(m);
            Ry += rowm[h];
        }

        float Nx = 0.f, Rx = 0.f;
        for (int w = bx.z + lane; w < bx.w; w += 32) {
            float m0 = -1e30f, m1 = -1e30f;
            int h = bx.x;
            for (; h + 1 < bx.y; h += 2) {
                m0 = fmaxf(m0, tile_ld(tile, h, w));
                m1 = fmaxf(m1, tile_ld(tile, h + 1, w));
            }
            if (h < bx.y) m0 = fmaxf(m0, tile_ld(tile, h, w));
            Nx += sigmoidf_fast(fmaxf(m0, m1));
            Rx += colm[w];
        }

        #pragma unroll
        for (int o = 16; o >= 1; o >>= 1) {
            Ny += __shfl_xor_sync(0xffffffffu, Ny, o);
            Ry += __shfl_xor_sync(0xffffffffu, Ry, o);
            Nx += __shfl_xor_sync(0xffffffffu, Nx, o);
            Rx += __shfl_xor_sync(0xffffffffu, Rx, o);
        }
        if (lane == 0) {
            float4 o;
            o.x = Ny;
            o.y = Ny + sumY - Ry;   // Sy
            o.z = Nx;
            o.w = Nx + sumX - Rx;   // Sx
            d_part[blk * GG + g] = o;
        }
    }
}

// ---------------------------------------------------------------------------
// Kernel 3: finalize. softmax gather + dice assembly. tgt_ids is int32.
// ---------------------------------------------------------------------------
__global__ __launch_bounds__(256) void final_kernel(
    const float* __restrict__ logits,
    const int* __restrict__ tgt_ids,
    float* __restrict__ out)
{
    const int idx = blockIdx.x * blockDim.x + threadIdx.x;
    if (idx >= BB * QQ * GG) return;
    const int g  = idx % GG;
    const int bq = idx / GG;
    const int b  = bq / QQ;

    const float* lg = logits + (size_t)bq * NC;
    float mx = lg[0];
    #pragma unroll
    for (int c = 1; c < NC; ++c) mx = fmaxf(mx, lg[c]);
    float se = 0.f;
    #pragma unroll
    for (int c = 0; c < NC; ++c) se += __expf(lg[c] - mx);
    const int cls = tgt_ids[b * GG + g];
    const float prob = __expf(lg[cls] - mx) / se;

    float Ny = 0.f, Sy = 0.f, Nx = 0.f, Sx = 0.f, Ty = 0.f, Tx = 0.f;
    #pragma unroll
    for (int t = 0; t < TT; ++t) {
        float4 p = d_part[(bq * TT + t) * GG + g];
        Ny += p.x; Sy += p.y; Nx += p.z; Sx += p.w;
        int4 bx = combine_box(((b * GG + g) * TT + t) * NCHUNK);
        Ty += (float)(bx.y - bx.x);
        Tx += (float)(bx.w - bx.z);
    }
    const float dice_y = 1.f - (2.f * Ny + 1.f) / (Sy + Ty + 1.f);
    const float dice_x = 1.f - (2.f * Nx + 1.f) / (Sx + Tx + 1.f);

    out[idx] = 2.f * (-prob) + 5.f * (dice_y + dice_x);
}

// ---------------------------------------------------------------------------
extern "C" void kernel_launch(void* const* d_in, const int* in_sizes, int n_in,
                              void* d_out, int out_size) {
    const float* pred_logits = (const float*)d_in[0];      // (B,Q,C)
    const float* pred_masks  = (const float*)d_in[1];      // (B,Q,T,H,W)
    const float* box_masks   = (const float*)d_in[2];      // (B,G,T,H,W)
    const int*   tgt_ids     = (const int*)d_in[3];        // (B,G) int32
    float* out = (float*)d_out;                            // (B,Q,G)

    box_chunk_kernel<<<NBGT * NCHUNK, 256>>>(box_masks);
    main_kernel<<<BB * QQ * TT, 256>>>(pred_masks);
    final_kernel<<<(BB * QQ * GG + 255) / 256, 256>>>(pred_logits, tgt_ids, out);
}

// round 6
// speedup vs baseline: 1.0390x; 1.0390x over previous
#include <cuda_runtime.h>
#include <cuda_fp16.h>
#include <cstdint>

#define BB 2
#define QQ 100
#define GG 10
#define TT 5
#define HH 128
#define WW 128
#define NC 41
#define NBGT (BB * GG * TT)      // 100
#define NCHUNK 8                 // row-chunks per box tile (16 rows each)

// Scratch (no cudaMalloc allowed)
__device__ int4   d_boxpart[NBGT * NCHUNK];   // raw (ymin,ymax,xmin,xmax) per chunk
__device__ float4 d_part[BB * QQ * TT * GG];  // Ny, Sy, Nx, Sx per (b,q,t,g)

__device__ __forceinline__ float sigmoidf_fast(float x) {
    return 1.0f / (1.0f + __expf(-x));
}

// Combine chunk partials -> final (y0,y1,x0,x1) box (0,0,0,0 if empty).
__device__ __forceinline__ int4 combine_box(int base) {
    int4 r = d_boxpart[base];
    #pragma unroll
    for (int c = 1; c < NCHUNK; ++c) {
        int4 p = d_boxpart[base + c];
        r.x = min(r.x, p.x); r.y = max(r.y, p.y);
        r.z = min(r.z, p.z); r.w = max(r.w, p.w);
    }
    return (r.y < 0) ? make_int4(0, 0, 0, 0) : make_int4(r.x, r.y + 1, r.z, r.w + 1);
}

// ---------------------------------------------------------------------------
// fp16 tile addressing. Row = 256 bytes (128 halfs) = 16 granules of 16B.
// Physical granule = logical ^ (h & 15)  (SW128-style, conflict-free for
// row-major 16B ld/st, column access, and lanes-across-rows).
// ---------------------------------------------------------------------------
__device__ __forceinline__ int tile_off16(int h, int g8) {       // byte offset of granule
    return (h << 8) + ((g8 ^ (h & 15)) << 4);
}
__device__ __forceinline__ float tile_ld_h(const char* t, int h, int w) {
    const int off = tile_off16(h, w >> 3) + ((w & 7) << 1);
    return __half2float(*reinterpret_cast<const __half*>(t + off));
}

// ---------------------------------------------------------------------------
// Kernel 1: box partials. grid = B*G*T*8 CTAs, 256 threads, 16 rows each.
// ---------------------------------------------------------------------------
__global__ __launch_bounds__(256) void box_chunk_kernel(const float* __restrict__ bm) {
    __shared__ int4 wred[8];
    const int tid   = threadIdx.x;
    const int lane  = tid & 31;
    const int wid   = tid >> 5;
    const int bgt   = blockIdx.x >> 3;
    const int chunk = blockIdx.x & 7;
    const int row0  = chunk * 16;

    const float4* src = reinterpret_cast<const float4*>(
        bm + (size_t)bgt * (HH * WW) + (size_t)row0 * WW);

    float4 vv[2];
    #pragma unroll
    for (int k = 0; k < 2; ++k) vv[k] = src[k * 256 + tid];

    const int c0 = lane * 4;
    int ymin = HH, ymax = -1, xmin = WW, xmax = -1;
    #pragma unroll
    for (int k = 0; k < 2; ++k) {
        const int row = row0 + k * 8 + wid;
        float4 d = vv[k];
        const bool f0 = d.x > 0.5f, f1 = d.y > 0.5f, f2 = d.z > 0.5f, f3 = d.w > 0.5f;
        xmin = min(xmin, f0 ? c0     : WW);
        xmin = min(xmin, f1 ? c0 + 1 : WW);
        xmin = min(xmin, f2 ? c0 + 2 : WW);
        xmin = min(xmin, f3 ? c0 + 3 : WW);
        xmax = max(xmax, f0 ? c0     : -1);
        xmax = max(xmax, f1 ? c0 + 1 : -1);
        xmax = max(xmax, f2 ? c0 + 2 : -1);
        xmax = max(xmax, f3 ? c0 + 3 : -1);
        const bool any = f0 | f1 | f2 | f3;
        ymin = min(ymin, any ? row : HH);
        ymax = max(ymax, any ? row : -1);
    }
    #pragma unroll
    for (int o = 16; o >= 1; o >>= 1) {
        ymin = min(ymin, __shfl_xor_sync(0xffffffffu, ymin, o));
        ymax = max(ymax, __shfl_xor_sync(0xffffffffu, ymax, o));
        xmin = min(xmin, __shfl_xor_sync(0xffffffffu, xmin, o));
        xmax = max(xmax, __shfl_xor_sync(0xffffffffu, xmax, o));
    }
    if (lane == 0) wred[wid] = make_int4(ymin, ymax, xmin, xmax);
    __syncthreads();
    if (wid == 0) {
        int4 r = wred[lane & 7];
        #pragma unroll
        for (int o = 4; o >= 1; o >>= 1) {
            r.x = min(r.x, __shfl_xor_sync(0xffffffffu, r.x, o));
            r.y = max(r.y, __shfl_xor_sync(0xffffffffu, r.y, o));
            r.z = min(r.z, __shfl_xor_sync(0xffffffffu, r.z, o));
            r.w = max(r.w, __shfl_xor_sync(0xffffffffu, r.w, o));
        }
        if (lane == 0) d_boxpart[blockIdx.x] = r;   // raw partial
    }
}

// ---------------------------------------------------------------------------
// Kernel 2: main reduction. grid = B*Q*T, 256 threads, 4 CTAs/SM (2 waves).
// fp16 swizzled tile (32 KB); fp32 row/col maxes from load registers.
// ---------------------------------------------------------------------------
__global__ __launch_bounds__(256, 4) void main_kernel(const float* __restrict__ pm) {
    __shared__ uint2  tile8[HH * 32];      // 32 KB fp16 tile (8B per 4 cols)
    __shared__ float4 colpart4[8 * 32];
    __shared__ float  rowm[HH];
    __shared__ float  colm[WW];
    __shared__ float  sums[2];
    __shared__ int4   sbox[GG * TT];
    const char* tileb = reinterpret_cast<const char*>(tile8);
    float* colpart = reinterpret_cast<float*>(colpart4);

    const int blk  = blockIdx.x;           // (b*Q + q)*T + t
    const int t    = blk % TT;
    const int bq   = blk / TT;
    const int b    = bq / QQ;
    const int tid  = threadIdx.x;
    const int lane = tid & 31;
    const int wid  = tid >> 5;

    // ---- combine box partials for this batch (overlaps with loads below) ----
    if (tid < GG * TT) {
        sbox[tid] = combine_box((b * GG * TT + tid) * NCHUNK);
    }

    // ---- phase 1: stream tile; fold row maxes (shfl) + col maxes (regs) ----
    const float4* src = reinterpret_cast<const float4*>(pm + (size_t)blk * (HH * WW));
    float4 cm = make_float4(-1e30f, -1e30f, -1e30f, -1e30f);
    float4 v[8];
    #pragma unroll
    for (int batch = 0; batch < 2; ++batch) {
        #pragma unroll
        for (int j2 = 0; j2 < 8; ++j2) v[j2] = src[(batch * 8 + j2) * 256 + tid];
        #pragma unroll
        for (int j2 = 0; j2 < 8; ++j2) {
            const int row = (batch * 8 + j2) * 8 + wid;
            float4 d = v[j2];
            // fp16 store: lane covers cols 4*lane..4*lane+3 -> half of granule lane>>1
            {
                __half2 lo = __floats2half2_rn(d.x, d.y);
                __half2 hi = __floats2half2_rn(d.z, d.w);
                uint2 pk;
                pk.x = *reinterpret_cast<uint32_t*>(&lo);
                pk.y = *reinterpret_cast<uint32_t*>(&hi);
                const int off = tile_off16(row, lane >> 1) + ((lane & 1) << 3);
                *reinterpret_cast<uint2*>(const_cast<char*>(tileb) + off) = pk;
            }
            cm.x = fmaxf(cm.x, d.x); cm.y = fmaxf(cm.y, d.y);
            cm.z = fmaxf(cm.z, d.z); cm.w = fmaxf(cm.w, d.w);
            float m = fmaxf(fmaxf(d.x, d.y), fmaxf(d.z, d.w));
            #pragma unroll
            for (int o = 16; o >= 1; o >>= 1) m = fmaxf(m, __shfl_xor_sync(0xffffffffu, m, o));
            if (lane == 0) rowm[row] = m;
        }
    }
    colpart4[wid * 32 + lane] = cm;
    __syncthreads();

    // ---- combine col partials + sigmoid row/col maxes ----
    if (tid < 128) {
        float m = colpart[tid];
        #pragma unroll
        for (int w = 1; w < 8; ++w) m = fmaxf(m, colpart[w * 128 + tid]);
        colm[tid] = sigmoidf_fast(m);
    } else {
        const int r = tid - 128;
        rowm[r] = sigmoidf_fast(rowm[r]);
    }
    __syncthreads();

    // ---- full sums of sigmoided row/col maxes ----
    if (wid < 2) {
        const float* arr = (wid == 0) ? rowm : colm;
        float s = arr[lane] + arr[lane + 32] + arr[lane + 64] + arr[lane + 96];
        #pragma unroll
        for (int o = 16; o >= 1; o >>= 1) s += __shfl_xor_sync(0xffffffffu, s, o);
        if (lane == 0) sums[wid] = s;
    }
    __syncthreads();
    const float sumY = sums[0];
    const float sumX = sums[1];

    // ---- per-target box-restricted reductions (one warp per g) ----
    for (int g = wid; g < GG; g += 8) {
        const int4 bx = sbox[g * TT + t];            // y0,y1,x0,x1

        // row maxes over x-range: 8 cols per LDS.128
        float Ny = 0.f, Ry = 0.f;
        const int g80 = bx.z >> 3;
        const int g81 = (bx.w - 1) >> 3;
        for (int h = bx.x + lane; h < bx.y; h += 32) {
            float m = -1e30f;
            for (int g8 = g80; g8 <= g81; ++g8) {
                const uint4 u = *reinterpret_cast<const uint4*>(tileb + tile_off16(h, g8));
                const int wb = g8 << 3;
                float2 f0 = __half22float2(*reinterpret_cast<const __half2*>(&u.x));
                float2 f1 = __half22float2(*reinterpret_cast<const __half2*>(&u.y));
                float2 f2 = __half22float2(*reinterpret_cast<const __half2*>(&u.z));
                float2 f3 = __half22float2(*reinterpret_cast<const __half2*>(&u.w));
                m = fmaxf(m, (wb     >= bx.z && wb     < bx.w) ? f0.x : -1e30f);
                m = fmaxf(m, (wb + 1 >= bx.z && wb + 1 < bx.w) ? f0.y : -1e30f);
                m = fmaxf(m, (wb + 2 >= bx.z && wb + 2 < bx.w) ? f1.x : -1e30f);
                m = fmaxf(m, (wb + 3 >= bx.z && wb + 3 < bx.w) ? f1.y : -1e30f);
                m = fmaxf(m, (wb + 4 >= bx.z && wb + 4 < bx.w) ? f2.x : -1e30f);
                m = fmaxf(m, (wb + 5 >= bx.z && wb + 5 < bx.w) ? f2.y : -1e30f);
                m = fmaxf(m, (wb + 6 >= bx.z && wb + 6 < bx.w) ? f3.x : -1e30f);
                m = fmaxf(m, (wb + 7 >= bx.z && wb + 7 < bx.w) ? f3.y : -1e30f);
            }
            Ny += sigmoidf_fast(m);
            Ry += rowm[h];
        }

        // col maxes over y-range
        float Nx = 0.f, Rx = 0.f;
        for (int w = bx.z + lane; w < bx.w; w += 32) {
            float m0 = -1e30f, m1 = -1e30f;
            int h = bx.x;
            for (; h + 1 < bx.y; h += 2) {
                m0 = fmaxf(m0, tile_ld_h(tileb, h, w));
                m1 = fmaxf(m1, tile_ld_h(tileb, h + 1, w));
            }
            if (h < bx.y) m0 = fmaxf(m0, tile_ld_h(tileb, h, w));
            Nx += sigmoidf_fast(fmaxf(m0, m1));
            Rx += colm[w];
        }

        #pragma unroll
        for (int o = 16; o >= 1; o >>= 1) {
            Ny += __shfl_xor_sync(0xffffffffu, Ny, o);
            Ry += __shfl_xor_sync(0xffffffffu, Ry, o);
            Nx += __shfl_xor_sync(0xffffffffu, Nx, o);
            Rx += __shfl_xor_sync(0xffffffffu, Rx, o);
        }
        if (lane == 0) {
            float4 o;
            o.x = Ny;
            o.y = Ny + sumY - Ry;   // Sy
            o.z = Nx;
            o.w = Nx + sumX - Rx;   // Sx
            d_part[blk * GG + g] = o;
        }
    }
}

// ---------------------------------------------------------------------------
// Kernel 3: finalize. softmax gather + dice assembly. tgt_ids is int32.
// ---------------------------------------------------------------------------
__global__ __launch_bounds__(64) void final_kernel(
    const float* __restrict__ logits,
    const int* __restrict__ tgt_ids,
    float* __restrict__ out)
{
    const int idx = blockIdx.x * blockDim.x + threadIdx.x;
    if (idx >= BB * QQ * GG) return;
    const int g  = idx % GG;
    const int bq = idx / GG;
    const int b  = bq / QQ;

    const float* lg = logits + (size_t)bq * NC;
    float mx = lg[0];
    #pragma unroll
    for (int c = 1; c < NC; ++c) mx = fmaxf(mx, lg[c]);
    float se = 0.f;
    #pragma unroll
    for (int c = 0; c < NC; ++c) se += __expf(lg[c] - mx);
    const int cls = tgt_ids[b * GG + g];
    const float prob = __expf(lg[cls] - mx) / se;

    float Ny = 0.f, Sy = 0.f, Nx = 0.f, Sx = 0.f, Ty = 0.f, Tx = 0.f;
    #pragma unroll
    for (int t = 0; t < TT; ++t) {
        float4 p = d_part[(bq * TT + t) * GG + g];
        Ny += p.x; Sy += p.y; Nx += p.z; Sx += p.w;
        int4 bx = combine_box(((b * GG + g) * TT + t) * NCHUNK);
        Ty += (float)(bx.y - bx.x);
        Tx += (float)(bx.w - bx.z);
    }
    const float dice_y = 1.f - (2.f * Ny + 1.f) / (Sy + Ty + 1.f);
    const float dice_x = 1.f - (2.f * Nx + 1.f) / (Sx + Tx + 1.f);

    out[idx] = 2.f * (-prob) + 5.f * (dice_y + dice_x);
}

// ---------------------------------------------------------------------------
extern "C" void kernel_launch(void* const* d_in, const int* in_sizes, int n_in,
                              void* d_out, int out_size) {
    const float* pred_logits = (const float*)d_in[0];      // (B,Q,C)
    const float* pred_masks  = (const float*)d_in[1];      // (B,Q,T,H,W)
    const float* box_masks   = (const float*)d_in[2];      // (B,G,T,H,W)
    const int*   tgt_ids     = (const int*)d_in[3];        // (B,G) int32
    float* out = (float*)d_out;                            // (B,Q,G)

    box_chunk_kernel<<<NBGT * NCHUNK, 256>>>(box_masks);
    main_kernel<<<BB * QQ * TT, 256>>>(pred_masks);
    final_kernel<<<(BB * QQ * GG + 63) / 64, 64>>>(pred_logits, tgt_ids, out);
}